// round 1
// baseline (speedup 1.0000x reference)
#include <cuda_runtime.h>
#include <math.h>

#define NPATCH 196
#define BLOCK  224   // 7 warps; threads 196..223 idle in compute, join reduction with zeros

__global__ __launch_bounds__(BLOCK)
void quanv_fused_kernel(const float* __restrict__ x,
                        const float* __restrict__ emb_W,
                        const float* __restrict__ emb_b,
                        const float* __restrict__ q_params,
                        const float* __restrict__ lin_W,
                        const float* __restrict__ lin_b,
                        float* __restrict__ out)
{
    __shared__ float simg[784];
    __shared__ float swarp[7][10];
    __shared__ float slogit[10];

    const int b   = blockIdx.x;
    const int tid = threadIdx.x;

    // coalesced image load: 784 floats
    for (int k = tid; k < 784; k += BLOCK)
        simg[k] = x[b * 784 + k];
    __syncthreads();

    float l[10];
#pragma unroll
    for (int c = 0; c < 10; c++) l[c] = 0.f;

    if (tid < NPATCH) {
        const int pr = tid / 14, pc = tid % 14;
        const float p0 = simg[(2 * pr) * 28 + 2 * pc];
        const float p1 = simg[(2 * pr) * 28 + 2 * pc + 1];
        const float p2 = simg[(2 * pr + 1) * 28 + 2 * pc];
        const float p3 = simg[(2 * pr + 1) * 28 + 2 * pc + 1];

        // angles = patch @ emb_W^T + emb_b
        float ang[4];
#pragma unroll
        for (int j = 0; j < 4; j++)
            ang[j] = emb_b[j]
                   + p0 * emb_W[j * 4 + 0] + p1 * emb_W[j * 4 + 1]
                   + p2 * emb_W[j * 4 + 2] + p3 * emb_W[j * 4 + 3];

        // initial product state after RY(ang_w) on |0000>
        float cw[4], sw[4];
#pragma unroll
        for (int j = 0; j < 4; j++)
            sincosf(0.5f * ang[j], &sw[j], &cw[j]);

        // amplitude index i = q0*8 + q1*4 + q2*2 + q3
        float a01[4] = { cw[0]*cw[1], cw[0]*sw[1], sw[0]*cw[1], sw[0]*sw[1] };
        float a23[4] = { cw[2]*cw[3], cw[2]*sw[3], sw[2]*cw[3], sw[2]*sw[3] };
        float sr[16], si[16];
#pragma unroll
        for (int i = 0; i < 16; i++) { sr[i] = a01[i >> 2] * a23[i & 3]; si[i] = 0.f; }

        // parameterized gate angles (uniform across threads; L1-broadcast)
        float qc[5], qs[5];
#pragma unroll
        for (int k = 0; k < 5; k++)
            sincosf(0.5f * q_params[k], &qs[k], &qc[k]);

        // ---- RX(q0) on wire 0 (stride 8) ----
        {
            const float c = qc[0], s = qs[0];
#pragma unroll
            for (int i = 0; i < 8; i++) {
                float ar = sr[i], ai = si[i], br = sr[i + 8], bi = si[i + 8];
                sr[i]     = c * ar + s * bi;
                si[i]     = c * ai - s * br;
                sr[i + 8] = c * br + s * ai;
                si[i + 8] = c * bi - s * ar;
            }
        }
        // ---- RY(q1) on wire 1 (stride 4) ----
        {
            const float c = qc[1], s = qs[1];
#pragma unroll
            for (int i = 0; i < 16; i++) {
                if ((i & 4) == 0) {
                    float ar = sr[i], ai = si[i], br = sr[i + 4], bi = si[i + 4];
                    sr[i]     = c * ar - s * br;
                    si[i]     = c * ai - s * bi;
                    sr[i + 4] = s * ar + c * br;
                    si[i + 4] = s * ai + c * bi;
                }
            }
        }
        // ---- RZ(q2) on wire 2 (stride 2): e = cos - i sin ; conj for q2=1 ----
        {
            const float er = qc[2], sz = qs[2];
#pragma unroll
            for (int i = 0; i < 16; i++) {
                const float ei = ((i >> 1) & 1) ? sz : -sz;
                float r = sr[i], m = si[i];
                sr[i] = r * er - m * ei;
                si[i] = r * ei + m * er;
            }
        }
        // ---- CNOT(0,1): q0=1 -> flip q1 : swap (i, i+4) for i in {8..11} ----
#pragma unroll
        for (int i = 8; i < 12; i++) {
            float tr = sr[i], ti = si[i];
            sr[i] = sr[i + 4]; si[i] = si[i + 4];
            sr[i + 4] = tr;    si[i + 4] = ti;
        }
        // ---- RX(q3) on wire 3 (stride 1) ----
        {
            const float c = qc[3], s = qs[3];
#pragma unroll
            for (int i = 0; i < 16; i += 2) {
                float ar = sr[i], ai = si[i], br = sr[i + 1], bi = si[i + 1];
                sr[i]     = c * ar + s * bi;
                si[i]     = c * ai - s * br;
                sr[i + 1] = c * br + s * ai;
                si[i + 1] = c * bi - s * ar;
            }
        }
        // ---- CNOT(2,3): q2=1 -> flip q3 : swap (i, i+1) for i in {2,6,10,14} ----
#pragma unroll
        for (int i = 2; i < 16; i += 4) {
            float tr = sr[i], ti = si[i];
            sr[i] = sr[i + 1]; si[i] = si[i + 1];
            sr[i + 1] = tr;    si[i + 1] = ti;
        }
        // ---- RY(q4) on wire 2 (stride 2) ----
        {
            const float c = qc[4], s = qs[4];
#pragma unroll
            for (int i = 0; i < 16; i++) {
                if ((i & 2) == 0) {
                    float ar = sr[i], ai = si[i], br = sr[i + 2], bi = si[i + 2];
                    sr[i]     = c * ar - s * br;
                    si[i]     = c * ai - s * bi;
                    sr[i + 2] = s * ar + c * br;
                    si[i + 2] = s * ai + c * bi;
                }
            }
        }
        // ---- CNOT(1,2): q1=1 -> flip q2 : swap (i, i+2) for i in {4,5,12,13} ----
#pragma unroll
        for (int i = 0; i < 16; i++) {
            if ((i & 4) && ((i & 2) == 0)) {
                float tr = sr[i], ti = si[i];
                sr[i] = sr[i + 2]; si[i] = si[i + 2];
                sr[i + 2] = tr;    si[i + 2] = ti;
            }
        }

        // ---- measure <Z_w> ----
        float e0 = 0.f, e1 = 0.f, e2 = 0.f, e3 = 0.f;
#pragma unroll
        for (int i = 0; i < 16; i++) {
            const float v = sr[i] * sr[i] + si[i] * si[i];
            e0 += (i & 8) ? -v : v;
            e1 += (i & 4) ? -v : v;
            e2 += (i & 2) ? -v : v;
            e3 += (i & 1) ? -v : v;
        }

        // ---- partial logits: feats[b, tid*4 + w] * lin_W[c, tid*4 + w] ----
        const float4* lw4 = (const float4*)lin_W;  // lin_W[c*784 + tid*4] == lw4[c*196 + tid]
#pragma unroll
        for (int c = 0; c < 10; c++) {
            const float4 w = __ldg(&lw4[c * NPATCH + tid]);
            l[c] = e0 * w.x + e1 * w.y + e2 * w.z + e3 * w.w;
        }
    }

    // ---- deterministic reduction of 10 logits over the block ----
#pragma unroll
    for (int off = 16; off > 0; off >>= 1)
#pragma unroll
        for (int c = 0; c < 10; c++)
            l[c] += __shfl_down_sync(0xffffffffu, l[c], off);

    const int warp = tid >> 5, lane = tid & 31;
    if (lane == 0)
#pragma unroll
        for (int c = 0; c < 10; c++) swarp[warp][c] = l[c];
    __syncthreads();

    if (tid < 10) {
        float s = lin_b[tid];
#pragma unroll
        for (int w = 0; w < 7; w++) s += swarp[w][tid];
        slogit[tid] = s;
    }
    __syncthreads();

    if (tid == 0) {
        float mx = slogit[0];
#pragma unroll
        for (int c = 1; c < 10; c++) mx = fmaxf(mx, slogit[c]);
        float se = 0.f;
#pragma unroll
        for (int c = 0; c < 10; c++) se += expf(slogit[c] - mx);
        const float lse = mx + logf(se);
#pragma unroll
        for (int c = 0; c < 10; c++) out[b * 10 + c] = slogit[c] - lse;
    }
}

extern "C" void kernel_launch(void* const* d_in, const int* in_sizes, int n_in,
                              void* d_out, int out_size)
{
    const float* x        = (const float*)d_in[0];
    const float* emb_W    = (const float*)d_in[1];
    const float* emb_b    = (const float*)d_in[2];
    const float* q_params = (const float*)d_in[3];
    const float* lin_W    = (const float*)d_in[4];
    const float* lin_b    = (const float*)d_in[5];
    float* out = (float*)d_out;

    const int B = in_sizes[0] / 784;
    quanv_fused_kernel<<<B, BLOCK>>>(x, emb_W, emb_b, q_params, lin_W, lin_b, out);
}

// round 2
// speedup vs baseline: 1.1971x; 1.1971x over previous
#include <cuda_runtime.h>
#include <math.h>

#define NPATCH 196
#define BLOCK  224   // 7 warps

// uniform circuit constants: {cos q0, q1, cos q4, sin q4 * cos q2, cos q3}
__device__ float g_qk[5];

__global__ void qprep_kernel(const float* __restrict__ q) {
    if (threadIdx.x == 0) {
        g_qk[0] = cosf(q[0]);
        g_qk[1] = q[1];
        g_qk[2] = cosf(q[4]);
        g_qk[3] = sinf(q[4]) * cosf(q[2]);
        g_qk[4] = cosf(q[3]);
    }
}

__global__ __launch_bounds__(BLOCK)
void quanv_fused_kernel(const float* __restrict__ x,
                        const float* __restrict__ emb_W,
                        const float* __restrict__ emb_b,
                        const float* __restrict__ lin_W,
                        const float* __restrict__ lin_b,
                        float* __restrict__ out)
{
    __shared__ float simg[784];
    __shared__ float part[BLOCK][11];   // padded: stride 11 coprime with 32 banks
    __shared__ float p2[10][8];
    __shared__ float slog[10];

    const int b   = blockIdx.x;
    const int tid = threadIdx.x;

    // coalesced image load: 196 float4 = 784 floats
    if (tid < NPATCH)
        ((float4*)simg)[tid] = ((const float4*)(x + b * 784))[tid];
    __syncthreads();

    float l[10];
#pragma unroll
    for (int c = 0; c < 10; c++) l[c] = 0.f;

    if (tid < NPATCH) {
        const int pr = tid / 14, pc = tid % 14;
        const float p0 = simg[(2 * pr) * 28 + 2 * pc];
        const float p1 = simg[(2 * pr) * 28 + 2 * pc + 1];
        const float p2v = simg[(2 * pr + 1) * 28 + 2 * pc];
        const float p3 = simg[(2 * pr + 1) * 28 + 2 * pc + 1];

        // angles = patch @ emb_W^T + emb_b
        float ang[4];
#pragma unroll
        for (int j = 0; j < 4; j++)
            ang[j] = fmaf(p0, emb_W[j * 4 + 0],
                     fmaf(p1, emb_W[j * 4 + 1],
                     fmaf(p2v, emb_W[j * 4 + 2],
                     fmaf(p3, emb_W[j * 4 + 3], emb_b[j]))));

        const float Kc0 = g_qk[0];   // cos q0
        const float Kq1 = g_qk[1];   // q1
        const float Kc4 = g_qk[2];   // cos q4
        const float Ks4 = g_qk[3];   // sin q4 * cos q2
        const float Kc3 = g_qk[4];   // cos q3

        // closed-form <Z_w> of the 4-qubit circuit
        const float ca0 = __cosf(ang[0]);
        const float ca1q = __cosf(ang[1] + Kq1);
        float sa2, ca2, sa3, ca3;
        __sincosf(ang[2], &sa2, &ca2);
        __sincosf(ang[3], &sa3, &ca3);

        const float e0 = Kc0 * ca0;
        const float e1 = e0 * ca1q;
        const float e2 = e1 * fmaf(Kc4, ca2, -Ks4 * sa2 * sa3);
        const float e3 = ca2 * (Kc3 * ca3);

        // partial logits: feats[b, tid*4 + w] * lin_W[c, tid*4 + w]
        const float4* lw4 = (const float4*)lin_W;   // lin_W[c*784 + 4*tid]
#pragma unroll
        for (int c = 0; c < 10; c++) {
            const float4 w = __ldg(&lw4[c * NPATCH + tid]);
            l[c] = fmaf(e0, w.x, fmaf(e1, w.y, fmaf(e2, w.z, e3 * w.w)));
        }
    }

    // ---- smem transpose reduction of 10 logits over the block ----
#pragma unroll
    for (int c = 0; c < 10; c++) part[tid][c] = l[c];
    __syncthreads();

    if (tid < 80) {
        const int c = tid >> 3, seg = tid & 7;
        float s = 0.f;
        const int r0 = seg * 28;
#pragma unroll
        for (int r = 0; r < 28; r++) s += part[r0 + r][c];
        p2[c][seg] = s;
    }
    __syncthreads();

    if (tid < 10) {
        float s = lin_b[tid];
#pragma unroll
        for (int k = 0; k < 8; k++) s += p2[tid][k];
        slog[tid] = s;
    }
    __syncthreads();

    if (tid < 10) {
        float mx = slog[0];
#pragma unroll
        for (int c = 1; c < 10; c++) mx = fmaxf(mx, slog[c]);
        float se = 0.f;
#pragma unroll
        for (int c = 0; c < 10; c++) se += __expf(slog[c] - mx);
        const float lse = mx + __logf(se);
        out[b * 10 + tid] = slog[tid] - lse;
    }
}

extern "C" void kernel_launch(void* const* d_in, const int* in_sizes, int n_in,
                              void* d_out, int out_size)
{
    const float* x        = (const float*)d_in[0];
    const float* emb_W    = (const float*)d_in[1];
    const float* emb_b    = (const float*)d_in[2];
    const float* q_params = (const float*)d_in[3];
    const float* lin_W    = (const float*)d_in[4];
    const float* lin_b    = (const float*)d_in[5];
    float* out = (float*)d_out;

    const int B = in_sizes[0] / 784;
    qprep_kernel<<<1, 32>>>(q_params);
    quanv_fused_kernel<<<B, BLOCK>>>(x, emb_W, emb_b, lin_W, lin_b, out);
}

// round 3
// speedup vs baseline: 1.6441x; 1.3734x over previous
#include <cuda_runtime.h>
#include <math.h>

#define NPATCH 196
#define BLOCK  224   // 7 full warps; threads 196..223 contribute zeros

__global__ __launch_bounds__(BLOCK)
void quanv_fused_kernel(const float* __restrict__ x,
                        const float* __restrict__ emb_W,
                        const float* __restrict__ emb_b,
                        const float* __restrict__ q_params,
                        const float* __restrict__ lin_W,
                        const float* __restrict__ lin_b,
                        float* __restrict__ out)
{
    __shared__ float swarp[7][10];
    __shared__ float slog[10];

    const int b   = blockIdx.x;
    const int tid = threadIdx.x;

    float l[10];
#pragma unroll
    for (int c = 0; c < 10; c++) l[c] = 0.f;

    if (tid < NPATCH) {
        // uniform circuit constants (broadcast loads + MUFU; identical across threads)
        const float Kc0 = __cosf(q_params[0]);           // cos q0
        const float Kq1 = q_params[1];                   // q1
        float s4, c4;
        __sincosf(q_params[4], &s4, &c4);                // sin/cos q4
        const float Ks4 = s4 * __cosf(q_params[2]);      // sin q4 * cos q2
        const float Kc3 = __cosf(q_params[3]);           // cos q3

        // direct coalesced pixel loads: two float2 per thread
        const int pr = tid / 14, pc = tid % 14;
        const float2 top = *(const float2*)(x + b * 784 + (2 * pr) * 28 + 2 * pc);
        const float2 bot = *(const float2*)(x + b * 784 + (2 * pr + 1) * 28 + 2 * pc);

        // angles = patch @ emb_W^T + emb_b  (emb rows as float4, uniform)
        float ang[4];
#pragma unroll
        for (int j = 0; j < 4; j++) {
            const float4 w = __ldg((const float4*)(emb_W + 4 * j));
            ang[j] = fmaf(top.x, w.x, fmaf(top.y, w.y,
                     fmaf(bot.x, w.z, fmaf(bot.y, w.w, emb_b[j]))));
        }

        // closed-form <Z_w> of the 4-qubit circuit
        const float ca0  = __cosf(ang[0]);
        const float ca1q = __cosf(ang[1] + Kq1);
        float sa2, ca2, sa3, ca3;
        __sincosf(ang[2], &sa2, &ca2);
        __sincosf(ang[3], &sa3, &ca3);

        const float e0 = Kc0 * ca0;
        const float e1 = e0 * ca1q;
        const float e2 = e1 * fmaf(c4, ca2, -Ks4 * sa2 * sa3);
        const float e3 = ca2 * (Kc3 * ca3);

        // partial logits: lin_W[c, 4*tid .. 4*tid+3]
        const float4* lw4 = (const float4*)lin_W;
#pragma unroll
        for (int c = 0; c < 10; c++) {
            const float4 w = __ldg(&lw4[c * NPATCH + tid]);
            l[c] = fmaf(e0, w.x, fmaf(e1, w.y, fmaf(e2, w.z, e3 * w.w)));
        }
    }

    // ---- warp butterfly reduction of 10 logits ----
#pragma unroll
    for (int off = 16; off > 0; off >>= 1)
#pragma unroll
        for (int c = 0; c < 10; c++)
            l[c] += __shfl_down_sync(0xffffffffu, l[c], off);

    const int warp = tid >> 5, lane = tid & 31;
    if (lane == 0)
#pragma unroll
        for (int c = 0; c < 10; c++) swarp[warp][c] = l[c];
    __syncthreads();

    if (tid < 10) {
        float s = lin_b[tid];
#pragma unroll
        for (int w = 0; w < 7; w++) s += swarp[w][tid];
        slog[tid] = s;
    }
    __syncthreads();

    if (tid < 10) {
        float mx = slog[0];
#pragma unroll
        for (int c = 1; c < 10; c++) mx = fmaxf(mx, slog[c]);
        float se = 0.f;
#pragma unroll
        for (int c = 0; c < 10; c++) se += __expf(slog[c] - mx);
        const float lse = mx + __logf(se);
        out[b * 10 + tid] = slog[tid] - lse;
    }
}

extern "C" void kernel_launch(void* const* d_in, const int* in_sizes, int n_in,
                              void* d_out, int out_size)
{
    const float* x        = (const float*)d_in[0];
    const float* emb_W    = (const float*)d_in[1];
    const float* emb_b    = (const float*)d_in[2];
    const float* q_params = (const float*)d_in[3];
    const float* lin_W    = (const float*)d_in[4];
    const float* lin_b    = (const float*)d_in[5];
    float* out = (float*)d_out;

    const int B = in_sizes[0] / 784;
    quanv_fused_kernel<<<B, BLOCK>>>(x, emb_W, emb_b, q_params, lin_W, lin_b, out);
}